// round 10
// baseline (speedup 1.0000x reference)
#include <cuda_runtime.h>
#include <cuda_bf16.h>

#define NNODES 50000
#define NEDGES 800000
#define DF 128
#define TM 128
#define TK 8
#define HS_STRIDE 132

// scatter-add accumulator (zeroed every launch)
__device__ float g_agg[(size_t)NNODES * DF];

// ---------------- FMA-only SiLU (no MUFU) ----------------
// sigmoid(|x|) = 1 / (1 + 2^(-|x|*log2e)); reflect for x<0.
// exp2 via round-split + degree-6 Taylor on [-0.5,0.5]; reciprocal via
// magic-constant seed + 3 Newton iterations. rel err ~1e-6.
__device__ __forceinline__ float fast_silu(float x) {
    float ax = fabsf(x);
    float t = fminf(ax * 1.4426950408889634f, 24.0f);   // t >= 0
    float k = t + 12582912.0f;                          // RN -> n = round(t)
    int   nb = __float_as_int(k) - 0x4B400000;          // n in [0,24]
    float f = t - (k - 12582912.0f);                    // f in [-0.5,0.5]
    float u = -f;
    float p = 1.5403530393381606e-4f;
    p = fmaf(p, u, 1.3333558146428443e-3f);
    p = fmaf(p, u, 9.6181291076284770e-3f);
    p = fmaf(p, u, 5.5504108664821580e-2f);
    p = fmaf(p, u, 2.4022650695910070e-1f);
    p = fmaf(p, u, 6.9314718055994530e-1f);
    p = fmaf(p, u, 1.0f);
    float e = p * __int_as_float((127 - nb) << 23);     // e = 2^(-t) in (0,1]
    float d = 1.0f + e;                                  // (1,2]
    float r = __int_as_float(0x7EF311C3 - __float_as_int(d));
    r = r * fmaf(-d, r, 2.0f);
    r = r * fmaf(-d, r, 2.0f);
    r = r * fmaf(-d, r, 2.0f);                           // r = 1/d
    float sig = (x >= 0.0f) ? r : (1.0f - r);
    return x * sig;
}

// packed dual-FMA (FFMA2) — only reachable via PTX fma.rn.f32x2
#define FMA2(c, a, b) asm("fma.rn.f32x2 %0, %1, %2, %0;" : "+l"(c) : "l"(a), "l"(b))

struct SmemLayout {
    float As[TK][TM];          // A tile, transposed [k][m]
    float Bs[TK][DF];          // B tile [k][n]
    float Hs[DF][HS_STRIDE];   // hidden, transposed [k][m], padded
    int   rows_s[TM];
    int   cols_s[TM];
};

// ---- shared micro-kernel body: 8x8 micro-tile, packed-pair accumulators ----
#define MICRO_FMA_BLOCK(A0, A1, BQ0, BQ1)                                   \
    do {                                                                    \
        float aval[8] = {A0.x, A0.y, A0.z, A0.w, A1.x, A1.y, A1.z, A1.w};   \
        _Pragma("unroll")                                                   \
        for (int _i = 0; _i < 8; ++_i) {                                    \
            unsigned long long ap;                                          \
            asm("mov.b64 %0, {%1, %1};" : "=l"(ap) : "f"(aval[_i]));        \
            FMA2(acc[_i][0], ap, BQ0.x);                                    \
            FMA2(acc[_i][1], ap, BQ0.y);                                    \
            FMA2(acc[_i][2], ap, BQ1.x);                                    \
            FMA2(acc[_i][3], ap, BQ1.y);                                    \
        }                                                                   \
    } while (0)

__global__ void zero_kernel() {
    size_t i = (size_t)blockIdx.x * blockDim.x + threadIdx.x;
    reinterpret_cast<float4*>(g_agg)[i] = make_float4(0.f, 0.f, 0.f, 0.f);
}

// ============================================================
// Edge kernel: e = silu(silu([h[row],h[col]] @ W1 + b1) @ W2 + b2)
//              red.v4 scatter into g_agg[row]
// ============================================================
__global__ void __launch_bounds__(256, 2)
edge_kernel(const float* __restrict__ h,
            const int* __restrict__ erow, const int* __restrict__ ecol,
            const float* __restrict__ W1, const float* __restrict__ b1,
            const float* __restrict__ W2, const float* __restrict__ b2)
{
    extern __shared__ char smem_raw[];
    SmemLayout& S = *reinterpret_cast<SmemLayout*>(smem_raw);
    const int tid = threadIdx.x;
    const int m0 = blockIdx.x * TM;
    const int tx = tid & 15, ty = tid >> 4;

    if (tid < TM) S.rows_s[tid] = erow[m0 + tid];
    else          S.cols_s[tid - TM] = ecol[m0 + tid - TM];
    __syncthreads();

    unsigned long long acc[8][4];
#pragma unroll
    for (int i = 0; i < 8; ++i)
#pragma unroll
        for (int jp = 0; jp < 4; ++jp) acc[i][jp] = 0ull;

    const int lm  = tid >> 1;          // A-load: edge within tile
    const int lkq = (tid & 1) * 4;     // A-load: k quad
    const int bk  = tid >> 5;          // B-load: k row
    const int bn  = (tid & 31) * 4;    // B-load: n quad

    // ---------- GEMM1: K = 256 (gathered A) ----------
    for (int kt = 0; kt < 32; ++kt) {
        const int gkbase = kt * TK;
        const int idx = (kt < 16) ? S.rows_s[lm] : S.cols_s[lm];
        const float4 av4 = *reinterpret_cast<const float4*>(
            h + (size_t)idx * DF + ((gkbase & 127) + lkq));
        const float4 bv4 = *reinterpret_cast<const float4*>(
            W1 + (size_t)(gkbase + bk) * DF + bn);
        __syncthreads();
        S.As[lkq + 0][lm] = av4.x;
        S.As[lkq + 1][lm] = av4.y;
        S.As[lkq + 2][lm] = av4.z;
        S.As[lkq + 3][lm] = av4.w;
        *reinterpret_cast<float4*>(&S.Bs[bk][bn]) = bv4;
        __syncthreads();
#pragma unroll
        for (int k = 0; k < TK; ++k) {
            const float4 a0 = *reinterpret_cast<const float4*>(&S.As[k][ty * 8]);
            const float4 a1 = *reinterpret_cast<const float4*>(&S.As[k][ty * 8 + 4]);
            const ulonglong2 bq0 = *reinterpret_cast<const ulonglong2*>(&S.Bs[k][tx * 8]);
            const ulonglong2 bq1 = *reinterpret_cast<const ulonglong2*>(&S.Bs[k][tx * 8 + 4]);
            MICRO_FMA_BLOCK(a0, a1, bq0, bq1);
        }
    }

    // ---------- epilogue 1: bias + silu -> Hs (transposed) ----------
    {
        const float4 bb0 = *reinterpret_cast<const float4*>(b1 + tx * 8);
        const float4 bb1 = *reinterpret_cast<const float4*>(b1 + tx * 8 + 4);
        const float bias[8] = {bb0.x, bb0.y, bb0.z, bb0.w, bb1.x, bb1.y, bb1.z, bb1.w};
        __syncthreads();   // all GEMM1 SMEM reads done
#pragma unroll
        for (int i = 0; i < 8; ++i) {
#pragma unroll
            for (int jp = 0; jp < 4; ++jp) {
                float lo, hi;
                asm("mov.b64 {%0, %1}, %2;" : "=f"(lo), "=f"(hi) : "l"(acc[i][jp]));
                lo = fast_silu(lo + bias[2 * jp]);
                hi = fast_silu(hi + bias[2 * jp + 1]);
                S.Hs[tx * 8 + 2 * jp][ty * 8 + i]     = lo;
                S.Hs[tx * 8 + 2 * jp + 1][ty * 8 + i] = hi;
                acc[i][jp] = 0ull;
            }
        }
        __syncthreads();
    }

    // ---------- GEMM2: K = 128 (A from Hs in SMEM) ----------
    for (int kt = 0; kt < 16; ++kt) {
        const float4 bv4 = *reinterpret_cast<const float4*>(
            W2 + (size_t)(kt * TK + bk) * DF + bn);
        __syncthreads();
        *reinterpret_cast<float4*>(&S.Bs[bk][bn]) = bv4;
        __syncthreads();
#pragma unroll
        for (int k = 0; k < TK; ++k) {
            const int gk = kt * TK + k;
            const float4 a0 = *reinterpret_cast<const float4*>(&S.Hs[gk][ty * 8]);
            const float4 a1 = *reinterpret_cast<const float4*>(&S.Hs[gk][ty * 8 + 4]);
            const ulonglong2 bq0 = *reinterpret_cast<const ulonglong2*>(&S.Bs[k][tx * 8]);
            const ulonglong2 bq1 = *reinterpret_cast<const ulonglong2*>(&S.Bs[k][tx * 8 + 4]);
            MICRO_FMA_BLOCK(a0, a1, bq0, bq1);
        }
    }

    // ---------- epilogue 2: bias + silu -> vectored red into g_agg ----------
    {
        const float4 cb0 = *reinterpret_cast<const float4*>(b2 + tx * 8);
        const float4 cb1 = *reinterpret_cast<const float4*>(b2 + tx * 8 + 4);
        const float bias[8] = {cb0.x, cb0.y, cb0.z, cb0.w, cb1.x, cb1.y, cb1.z, cb1.w};
#pragma unroll
        for (int i = 0; i < 8; ++i) {
            const int r = S.rows_s[ty * 8 + i];
            float* dst = g_agg + (size_t)r * DF + tx * 8;
            float e[8];
#pragma unroll
            for (int jp = 0; jp < 4; ++jp) {
                float lo, hi;
                asm("mov.b64 {%0, %1}, %2;" : "=f"(lo), "=f"(hi) : "l"(acc[i][jp]));
                e[2 * jp]     = fast_silu(lo + bias[2 * jp]);
                e[2 * jp + 1] = fast_silu(hi + bias[2 * jp + 1]);
            }
            asm volatile("red.global.add.v4.f32 [%0], {%1, %2, %3, %4};"
                         :: "l"(dst), "f"(e[0]), "f"(e[1]), "f"(e[2]), "f"(e[3]) : "memory");
            asm volatile("red.global.add.v4.f32 [%0], {%1, %2, %3, %4};"
                         :: "l"(dst + 4), "f"(e[4]), "f"(e[5]), "f"(e[6]), "f"(e[7]) : "memory");
        }
    }
}

// ============================================================
// Node kernel: out = h + (silu([h,agg] @ nW1 + nb1) @ nW2 + nb2)
// ============================================================
__global__ void __launch_bounds__(256, 2)
node_kernel(const float* __restrict__ h,
            const float* __restrict__ W1, const float* __restrict__ b1,
            const float* __restrict__ W2, const float* __restrict__ b2,
            float* __restrict__ out)
{
    extern __shared__ char smem_raw[];
    SmemLayout& S = *reinterpret_cast<SmemLayout*>(smem_raw);
    const int tid = threadIdx.x;
    const int m0 = blockIdx.x * TM;
    const int tx = tid & 15, ty = tid >> 4;

    unsigned long long acc[8][4];
#pragma unroll
    for (int i = 0; i < 8; ++i)
#pragma unroll
        for (int jp = 0; jp < 4; ++jp) acc[i][jp] = 0ull;

    const int lm  = tid >> 1;
    const int lkq = (tid & 1) * 4;
    const int bk  = tid >> 5;
    const int bn  = (tid & 31) * 4;
    const int nodeL = m0 + lm;
    const int nodeC = (nodeL < NNODES) ? nodeL : (NNODES - 1);

    // ---------- GEMM1: K = 256, A = [h | agg] ----------
    for (int kt = 0; kt < 32; ++kt) {
        const int gkbase = kt * TK;
        const float* src = (kt < 16)
            ? (h     + (size_t)nodeC * DF + gkbase + lkq)
            : (g_agg + (size_t)nodeC * DF + (gkbase - 128) + lkq);
        const float4 av4 = *reinterpret_cast<const float4*>(src);
        const float4 bv4 = *reinterpret_cast<const float4*>(
            W1 + (size_t)(gkbase + bk) * DF + bn);
        __syncthreads();
        S.As[lkq + 0][lm] = av4.x;
        S.As[lkq + 1][lm] = av4.y;
        S.As[lkq + 2][lm] = av4.z;
        S.As[lkq + 3][lm] = av4.w;
        *reinterpret_cast<float4*>(&S.Bs[bk][bn]) = bv4;
        __syncthreads();
#pragma unroll
        for (int k = 0; k < TK; ++k) {
            const float4 a0 = *reinterpret_cast<const float4*>(&S.As[k][ty * 8]);
            const float4 a1 = *reinterpret_cast<const float4*>(&S.As[k][ty * 8 + 4]);
            const ulonglong2 bq0 = *reinterpret_cast<const ulonglong2*>(&S.Bs[k][tx * 8]);
            const ulonglong2 bq1 = *reinterpret_cast<const ulonglong2*>(&S.Bs[k][tx * 8 + 4]);
            MICRO_FMA_BLOCK(a0, a1, bq0, bq1);
        }
    }

    // ---------- epilogue 1: bias + silu -> Hs ----------
    {
        const float4 bb0 = *reinterpret_cast<const float4*>(b1 + tx * 8);
        const float4 bb1 = *reinterpret_cast<const float4*>(b1 + tx * 8 + 4);
        const float bias[8] = {bb0.x, bb0.y, bb0.z, bb0.w, bb1.x, bb1.y, bb1.z, bb1.w};
        __syncthreads();
#pragma unroll
        for (int i = 0; i < 8; ++i) {
#pragma unroll
            for (int jp = 0; jp < 4; ++jp) {
                float lo, hi;
                asm("mov.b64 {%0, %1}, %2;" : "=f"(lo), "=f"(hi) : "l"(acc[i][jp]));
                lo = fast_silu(lo + bias[2 * jp]);
                hi = fast_silu(hi + bias[2 * jp + 1]);
                S.Hs[tx * 8 + 2 * jp][ty * 8 + i]     = lo;
                S.Hs[tx * 8 + 2 * jp + 1][ty * 8 + i] = hi;
                acc[i][jp] = 0ull;
            }
        }
        __syncthreads();
    }

    // ---------- GEMM2: K = 128 ----------
    for (int kt = 0; kt < 16; ++kt) {
        const float4 bv4 = *reinterpret_cast<const float4*>(
            W2 + (size_t)(kt * TK + bk) * DF + bn);
        __syncthreads();
        *reinterpret_cast<float4*>(&S.Bs[bk][bn]) = bv4;
        __syncthreads();
#pragma unroll
        for (int k = 0; k < TK; ++k) {
            const int gk = kt * TK + k;
            const float4 a0 = *reinterpret_cast<const float4*>(&S.Hs[gk][ty * 8]);
            const float4 a1 = *reinterpret_cast<const float4*>(&S.Hs[gk][ty * 8 + 4]);
            const ulonglong2 bq0 = *reinterpret_cast<const ulonglong2*>(&S.Bs[k][tx * 8]);
            const ulonglong2 bq1 = *reinterpret_cast<const ulonglong2*>(&S.Bs[k][tx * 8 + 4]);
            MICRO_FMA_BLOCK(a0, a1, bq0, bq1);
        }
    }

    // ---------- epilogue 2: bias + residual -> out (no silu) ----------
    {
        const float4 cb0 = *reinterpret_cast<const float4*>(b2 + tx * 8);
        const float4 cb1 = *reinterpret_cast<const float4*>(b2 + tx * 8 + 4);
        const float bias[8] = {cb0.x, cb0.y, cb0.z, cb0.w, cb1.x, cb1.y, cb1.z, cb1.w};
#pragma unroll
        for (int i = 0; i < 8; ++i) {
            const int node = m0 + ty * 8 + i;
            if (node < NNODES) {
                const float4 h0 = *reinterpret_cast<const float4*>(h + (size_t)node * DF + tx * 8);
                const float4 h1 = *reinterpret_cast<const float4*>(h + (size_t)node * DF + tx * 8 + 4);
                const float hres[8] = {h0.x, h0.y, h0.z, h0.w, h1.x, h1.y, h1.z, h1.w};
                float o[8];
#pragma unroll
                for (int jp = 0; jp < 4; ++jp) {
                    float lo, hi;
                    asm("mov.b64 {%0, %1}, %2;" : "=f"(lo), "=f"(hi) : "l"(acc[i][jp]));
                    o[2 * jp]     = lo + bias[2 * jp]     + hres[2 * jp];
                    o[2 * jp + 1] = hi + bias[2 * jp + 1] + hres[2 * jp + 1];
                }
                float4* dst = reinterpret_cast<float4*>(out + (size_t)node * DF + tx * 8);
                dst[0] = make_float4(o[0], o[1], o[2], o[3]);
                dst[1] = make_float4(o[4], o[5], o[6], o[7]);
            }
        }
    }
}

extern "C" void kernel_launch(void* const* d_in, const int* in_sizes, int n_in,
                              void* d_out, int out_size) {
    (void)in_sizes; (void)n_in; (void)out_size;
    const float* h    = (const float*)d_in[0];
    const int*   eidx = (const int*)d_in[1];   // [2, E]: row then col
    const float* eW1  = (const float*)d_in[2];
    const float* eb1  = (const float*)d_in[3];
    const float* eW2  = (const float*)d_in[4];
    const float* eb2  = (const float*)d_in[5];
    const float* nW1  = (const float*)d_in[6];
    const float* nb1  = (const float*)d_in[7];
    const float* nW2  = (const float*)d_in[8];
    const float* nb2  = (const float*)d_in[9];
    float* out = (float*)d_out;

    const int smem = (int)sizeof(SmemLayout);
    cudaFuncSetAttribute(edge_kernel, cudaFuncAttributeMaxDynamicSharedMemorySize, smem);
    cudaFuncSetAttribute(node_kernel, cudaFuncAttributeMaxDynamicSharedMemorySize, smem);

    zero_kernel<<<(NNODES * DF / 4 + 255) / 256, 256>>>();
    edge_kernel<<<NEDGES / TM, 256, smem>>>(h, eidx, eidx + NEDGES,
                                            eW1, eb1, eW2, eb2);
    node_kernel<<<(NNODES + TM - 1) / TM, 256, smem>>>(h, nW1, nb1, nW2, nb2, out);
}

// round 11
// speedup vs baseline: 1.0005x; 1.0005x over previous
#include <cuda_runtime.h>
#include <cuda_bf16.h>

#define NNODES 50000
#define NEDGES 800000
#define DF 128
#define TM 128
#define TK 8
#define HS_STRIDE 132

// scatter-add accumulator (zeroed every launch)
__device__ float g_agg[(size_t)NNODES * DF];

// ---------------- FMA-only SiLU (no MUFU) ----------------
// sigmoid(|x|) = 1 / (1 + 2^(-|x|*log2e)); reflect for x<0.
// exp2 via round-split + degree-6 Taylor on [-0.5,0.5]; reciprocal via
// magic-constant seed + 3 Newton iterations. rel err ~1e-6.
__device__ __forceinline__ float fast_silu(float x) {
    float ax = fabsf(x);
    float t = fminf(ax * 1.4426950408889634f, 24.0f);   // t >= 0
    float k = t + 12582912.0f;                          // RN -> n = round(t)
    int   nb = __float_as_int(k) - 0x4B400000;          // n in [0,24]
    float f = t - (k - 12582912.0f);                    // f in [-0.5,0.5]
    float u = -f;
    float p = 1.5403530393381606e-4f;
    p = fmaf(p, u, 1.3333558146428443e-3f);
    p = fmaf(p, u, 9.6181291076284770e-3f);
    p = fmaf(p, u, 5.5504108664821580e-2f);
    p = fmaf(p, u, 2.4022650695910070e-1f);
    p = fmaf(p, u, 6.9314718055994530e-1f);
    p = fmaf(p, u, 1.0f);
    float e = p * __int_as_float((127 - nb) << 23);     // e = 2^(-t) in (0,1]
    float d = 1.0f + e;                                  // (1,2]
    float r = __int_as_float(0x7EF311C3 - __float_as_int(d));
    r = r * fmaf(-d, r, 2.0f);
    r = r * fmaf(-d, r, 2.0f);
    r = r * fmaf(-d, r, 2.0f);                           // r = 1/d
    float sig = (x >= 0.0f) ? r : (1.0f - r);
    return x * sig;
}

// packed dual-FMA (FFMA2) — only reachable via PTX fma.rn.f32x2
#define FMA2(c, a, b) asm("fma.rn.f32x2 %0, %1, %2, %0;" : "+l"(c) : "l"(a), "l"(b))

struct SmemLayout {
    float As[TK][TM];          // A tile, transposed [k][m]
    float Bs[TK][DF];          // B tile [k][n]
    float Hs[DF][HS_STRIDE];   // hidden, transposed [k][m], padded
    int   rows_s[TM];
    int   cols_s[TM];
};

// ---- shared micro-kernel body: 8x8 micro-tile, packed-pair accumulators ----
#define MICRO_FMA_BLOCK(A0, A1, BQ0, BQ1)                                   \
    do {                                                                    \
        float aval[8] = {A0.x, A0.y, A0.z, A0.w, A1.x, A1.y, A1.z, A1.w};   \
        _Pragma("unroll")                                                   \
        for (int _i = 0; _i < 8; ++_i) {                                    \
            unsigned long long ap;                                          \
            asm("mov.b64 %0, {%1, %1};" : "=l"(ap) : "f"(aval[_i]));        \
            FMA2(acc[_i][0], ap, BQ0.x);                                    \
            FMA2(acc[_i][1], ap, BQ0.y);                                    \
            FMA2(acc[_i][2], ap, BQ1.x);                                    \
            FMA2(acc[_i][3], ap, BQ1.y);                                    \
        }                                                                   \
    } while (0)

__global__ void zero_kernel() {
    size_t i = (size_t)blockIdx.x * blockDim.x + threadIdx.x;
    reinterpret_cast<float4*>(g_agg)[i] = make_float4(0.f, 0.f, 0.f, 0.f);
}

// ============================================================
// Edge kernel: e = silu(silu([h[row],h[col]] @ W1 + b1) @ W2 + b2)
//              red.v4 scatter into g_agg[row]
// ============================================================
__global__ void __launch_bounds__(256, 2)
edge_kernel(const float* __restrict__ h,
            const int* __restrict__ erow, const int* __restrict__ ecol,
            const float* __restrict__ W1, const float* __restrict__ b1,
            const float* __restrict__ W2, const float* __restrict__ b2)
{
    extern __shared__ char smem_raw[];
    SmemLayout& S = *reinterpret_cast<SmemLayout*>(smem_raw);
    const int tid = threadIdx.x;
    const int m0 = blockIdx.x * TM;
    const int tx = tid & 15, ty = tid >> 4;

    if (tid < TM) S.rows_s[tid] = erow[m0 + tid];
    else          S.cols_s[tid - TM] = ecol[m0 + tid - TM];
    __syncthreads();

    unsigned long long acc[8][4];
#pragma unroll
    for (int i = 0; i < 8; ++i)
#pragma unroll
        for (int jp = 0; jp < 4; ++jp) acc[i][jp] = 0ull;

    const int lm  = tid >> 1;          // A-load: edge within tile
    const int lkq = (tid & 1) * 4;     // A-load: k quad
    const int bk  = tid >> 5;          // B-load: k row
    const int bn  = (tid & 31) * 4;    // B-load: n quad

    // ---------- GEMM1: K = 256 (gathered A) ----------
    for (int kt = 0; kt < 32; ++kt) {
        const int gkbase = kt * TK;
        const int idx = (kt < 16) ? S.rows_s[lm] : S.cols_s[lm];
        const float4 av4 = *reinterpret_cast<const float4*>(
            h + (size_t)idx * DF + ((gkbase & 127) + lkq));
        const float4 bv4 = *reinterpret_cast<const float4*>(
            W1 + (size_t)(gkbase + bk) * DF + bn);
        __syncthreads();
        S.As[lkq + 0][lm] = av4.x;
        S.As[lkq + 1][lm] = av4.y;
        S.As[lkq + 2][lm] = av4.z;
        S.As[lkq + 3][lm] = av4.w;
        *reinterpret_cast<float4*>(&S.Bs[bk][bn]) = bv4;
        __syncthreads();
#pragma unroll
        for (int k = 0; k < TK; ++k) {
            const float4 a0 = *reinterpret_cast<const float4*>(&S.As[k][ty * 8]);
            const float4 a1 = *reinterpret_cast<const float4*>(&S.As[k][ty * 8 + 4]);
            const ulonglong2 bq0 = *reinterpret_cast<const ulonglong2*>(&S.Bs[k][tx * 8]);
            const ulonglong2 bq1 = *reinterpret_cast<const ulonglong2*>(&S.Bs[k][tx * 8 + 4]);
            MICRO_FMA_BLOCK(a0, a1, bq0, bq1);
        }
    }

    // ---------- epilogue 1: bias + silu -> Hs (transposed) ----------
    {
        const float4 bb0 = *reinterpret_cast<const float4*>(b1 + tx * 8);
        const float4 bb1 = *reinterpret_cast<const float4*>(b1 + tx * 8 + 4);
        const float bias[8] = {bb0.x, bb0.y, bb0.z, bb0.w, bb1.x, bb1.y, bb1.z, bb1.w};
        __syncthreads();   // all GEMM1 SMEM reads done
#pragma unroll
        for (int i = 0; i < 8; ++i) {
#pragma unroll
            for (int jp = 0; jp < 4; ++jp) {
                float lo, hi;
                asm("mov.b64 {%0, %1}, %2;" : "=f"(lo), "=f"(hi) : "l"(acc[i][jp]));
                lo = fast_silu(lo + bias[2 * jp]);
                hi = fast_silu(hi + bias[2 * jp + 1]);
                S.Hs[tx * 8 + 2 * jp][ty * 8 + i]     = lo;
                S.Hs[tx * 8 + 2 * jp + 1][ty * 8 + i] = hi;
                acc[i][jp] = 0ull;
            }
        }
        __syncthreads();
    }

    // ---------- GEMM2: K = 128 (A from Hs in SMEM) ----------
    for (int kt = 0; kt < 16; ++kt) {
        const float4 bv4 = *reinterpret_cast<const float4*>(
            W2 + (size_t)(kt * TK + bk) * DF + bn);
        __syncthreads();
        *reinterpret_cast<float4*>(&S.Bs[bk][bn]) = bv4;
        __syncthreads();
#pragma unroll
        for (int k = 0; k < TK; ++k) {
            const int gk = kt * TK + k;
            const float4 a0 = *reinterpret_cast<const float4*>(&S.Hs[gk][ty * 8]);
            const float4 a1 = *reinterpret_cast<const float4*>(&S.Hs[gk][ty * 8 + 4]);
            const ulonglong2 bq0 = *reinterpret_cast<const ulonglong2*>(&S.Bs[k][tx * 8]);
            const ulonglong2 bq1 = *reinterpret_cast<const ulonglong2*>(&S.Bs[k][tx * 8 + 4]);
            MICRO_FMA_BLOCK(a0, a1, bq0, bq1);
        }
    }

    // ---------- epilogue 2: bias + silu -> vectored red into g_agg ----------
    {
        const float4 cb0 = *reinterpret_cast<const float4*>(b2 + tx * 8);
        const float4 cb1 = *reinterpret_cast<const float4*>(b2 + tx * 8 + 4);
        const float bias[8] = {cb0.x, cb0.y, cb0.z, cb0.w, cb1.x, cb1.y, cb1.z, cb1.w};
#pragma unroll
        for (int i = 0; i < 8; ++i) {
            const int r = S.rows_s[ty * 8 + i];
            float* dst = g_agg + (size_t)r * DF + tx * 8;
            float e[8];
#pragma unroll
            for (int jp = 0; jp < 4; ++jp) {
                float lo, hi;
                asm("mov.b64 {%0, %1}, %2;" : "=f"(lo), "=f"(hi) : "l"(acc[i][jp]));
                e[2 * jp]     = fast_silu(lo + bias[2 * jp]);
                e[2 * jp + 1] = fast_silu(hi + bias[2 * jp + 1]);
            }
            asm volatile("red.global.add.v4.f32 [%0], {%1, %2, %3, %4};"
                         :: "l"(dst), "f"(e[0]), "f"(e[1]), "f"(e[2]), "f"(e[3]) : "memory");
            asm volatile("red.global.add.v4.f32 [%0], {%1, %2, %3, %4};"
                         :: "l"(dst + 4), "f"(e[4]), "f"(e[5]), "f"(e[6]), "f"(e[7]) : "memory");
        }
    }
}

// ============================================================
// Node kernel: out = h + (silu([h,agg] @ nW1 + nb1) @ nW2 + nb2)
// ============================================================
__global__ void __launch_bounds__(256, 2)
node_kernel(const float* __restrict__ h,
            const float* __restrict__ W1, const float* __restrict__ b1,
            const float* __restrict__ W2, const float* __restrict__ b2,
            float* __restrict__ out)
{
    extern __shared__ char smem_raw[];
    SmemLayout& S = *reinterpret_cast<SmemLayout*>(smem_raw);
    const int tid = threadIdx.x;
    const int m0 = blockIdx.x * TM;
    const int tx = tid & 15, ty = tid >> 4;

    unsigned long long acc[8][4];
#pragma unroll
    for (int i = 0; i < 8; ++i)
#pragma unroll
        for (int jp = 0; jp < 4; ++jp) acc[i][jp] = 0ull;

    const int lm  = tid >> 1;
    const int lkq = (tid & 1) * 4;
    const int bk  = tid >> 5;
    const int bn  = (tid & 31) * 4;
    const int nodeL = m0 + lm;
    const int nodeC = (nodeL < NNODES) ? nodeL : (NNODES - 1);

    // ---------- GEMM1: K = 256, A = [h | agg] ----------
    for (int kt = 0; kt < 32; ++kt) {
        const int gkbase = kt * TK;
        const float* src = (kt < 16)
            ? (h     + (size_t)nodeC * DF + gkbase + lkq)
            : (g_agg + (size_t)nodeC * DF + (gkbase - 128) + lkq);
        const float4 av4 = *reinterpret_cast<const float4*>(src);
        const float4 bv4 = *reinterpret_cast<const float4*>(
            W1 + (size_t)(gkbase + bk) * DF + bn);
        __syncthreads();
        S.As[lkq + 0][lm] = av4.x;
        S.As[lkq + 1][lm] = av4.y;
        S.As[lkq + 2][lm] = av4.z;
        S.As[lkq + 3][lm] = av4.w;
        *reinterpret_cast<float4*>(&S.Bs[bk][bn]) = bv4;
        __syncthreads();
#pragma unroll
        for (int k = 0; k < TK; ++k) {
            const float4 a0 = *reinterpret_cast<const float4*>(&S.As[k][ty * 8]);
            const float4 a1 = *reinterpret_cast<const float4*>(&S.As[k][ty * 8 + 4]);
            const ulonglong2 bq0 = *reinterpret_cast<const ulonglong2*>(&S.Bs[k][tx * 8]);
            const ulonglong2 bq1 = *reinterpret_cast<const ulonglong2*>(&S.Bs[k][tx * 8 + 4]);
            MICRO_FMA_BLOCK(a0, a1, bq0, bq1);
        }
    }

    // ---------- epilogue 1: bias + silu -> Hs ----------
    {
        const float4 bb0 = *reinterpret_cast<const float4*>(b1 + tx * 8);
        const float4 bb1 = *reinterpret_cast<const float4*>(b1 + tx * 8 + 4);
        const float bias[8] = {bb0.x, bb0.y, bb0.z, bb0.w, bb1.x, bb1.y, bb1.z, bb1.w};
        __syncthreads();
#pragma unroll
        for (int i = 0; i < 8; ++i) {
#pragma unroll
            for (int jp = 0; jp < 4; ++jp) {
                float lo, hi;
                asm("mov.b64 {%0, %1}, %2;" : "=f"(lo), "=f"(hi) : "l"(acc[i][jp]));
                lo = fast_silu(lo + bias[2 * jp]);
                hi = fast_silu(hi + bias[2 * jp + 1]);
                S.Hs[tx * 8 + 2 * jp][ty * 8 + i]     = lo;
                S.Hs[tx * 8 + 2 * jp + 1][ty * 8 + i] = hi;
                acc[i][jp] = 0ull;
            }
        }
        __syncthreads();
    }

    // ---------- GEMM2: K = 128 ----------
    for (int kt = 0; kt < 16; ++kt) {
        const float4 bv4 = *reinterpret_cast<const float4*>(
            W2 + (size_t)(kt * TK + bk) * DF + bn);
        __syncthreads();
        *reinterpret_cast<float4*>(&S.Bs[bk][bn]) = bv4;
        __syncthreads();
#pragma unroll
        for (int k = 0; k < TK; ++k) {
            const int gk = kt * TK + k;
            const float4 a0 = *reinterpret_cast<const float4*>(&S.Hs[gk][ty * 8]);
            const float4 a1 = *reinterpret_cast<const float4*>(&S.Hs[gk][ty * 8 + 4]);
            const ulonglong2 bq0 = *reinterpret_cast<const ulonglong2*>(&S.Bs[k][tx * 8]);
            const ulonglong2 bq1 = *reinterpret_cast<const ulonglong2*>(&S.Bs[k][tx * 8 + 4]);
            MICRO_FMA_BLOCK(a0, a1, bq0, bq1);
        }
    }

    // ---------- epilogue 2: bias + residual -> out (no silu) ----------
    {
        const float4 cb0 = *reinterpret_cast<const float4*>(b2 + tx * 8);
        const float4 cb1 = *reinterpret_cast<const float4*>(b2 + tx * 8 + 4);
        const float bias[8] = {cb0.x, cb0.y, cb0.z, cb0.w, cb1.x, cb1.y, cb1.z, cb1.w};
#pragma unroll
        for (int i = 0; i < 8; ++i) {
            const int node = m0 + ty * 8 + i;
            if (node < NNODES) {
                const float4 h0 = *reinterpret_cast<const float4*>(h + (size_t)node * DF + tx * 8);
                const float4 h1 = *reinterpret_cast<const float4*>(h + (size_t)node * DF + tx * 8 + 4);
                const float hres[8] = {h0.x, h0.y, h0.z, h0.w, h1.x, h1.y, h1.z, h1.w};
                float o[8];
#pragma unroll
                for (int jp = 0; jp < 4; ++jp) {
                    float lo, hi;
                    asm("mov.b64 {%0, %1}, %2;" : "=f"(lo), "=f"(hi) : "l"(acc[i][jp]));
                    o[2 * jp]     = lo + bias[2 * jp]     + hres[2 * jp];
                    o[2 * jp + 1] = hi + bias[2 * jp + 1] + hres[2 * jp + 1];
                }
                float4* dst = reinterpret_cast<float4*>(out + (size_t)node * DF + tx * 8);
                dst[0] = make_float4(o[0], o[1], o[2], o[3]);
                dst[1] = make_float4(o[4], o[5], o[6], o[7]);
            }
        }
    }
}

extern "C" void kernel_launch(void* const* d_in, const int* in_sizes, int n_in,
                              void* d_out, int out_size) {
    (void)in_sizes; (void)n_in; (void)out_size;
    const float* h    = (const float*)d_in[0];
    const int*   eidx = (const int*)d_in[1];   // [2, E]: row then col
    const float* eW1  = (const float*)d_in[2];
    const float* eb1  = (const float*)d_in[3];
    const float* eW2  = (const float*)d_in[4];
    const float* eb2  = (const float*)d_in[5];
    const float* nW1  = (const float*)d_in[6];
    const float* nb1  = (const float*)d_in[7];
    const float* nW2  = (const float*)d_in[8];
    const float* nb2  = (const float*)d_in[9];
    float* out = (float*)d_out;

    const int smem = (int)sizeof(SmemLayout);
    cudaFuncSetAttribute(edge_kernel, cudaFuncAttributeMaxDynamicSharedMemorySize, smem);
    cudaFuncSetAttribute(node_kernel, cudaFuncAttributeMaxDynamicSharedMemorySize, smem);

    zero_kernel<<<(NNODES * DF / 4 + 255) / 256, 256>>>();
    edge_kernel<<<NEDGES / TM, 256, smem>>>(h, eidx, eidx + NEDGES,
                                            eW1, eb1, eW2, eb2);
    node_kernel<<<(NNODES + TM - 1) / TM, 256, smem>>>(h, nW1, nb1, nW2, nb2, out);
}